// round 7
// baseline (speedup 1.0000x reference)
#include <cuda_runtime.h>
#include <math.h>

#define SW   192
#define SHW  (192*192)
#define HP   188
#define NC   32
#define NB   2
#define EPS_F 1e-8f

// scratch: grand-sum accumulator + precomputed inverse depth (correctly rounded)
__device__ double g_sum;
__device__ float  g_invd[NB * SHW];

// Pre-pass: exact 1/(d+1e-6) per pixel (IEEE-rn, matches XLA f32 div), zero accumulator.
__global__ void prep_kernel(const float* __restrict__ depth) {
    int i = blockIdx.x * blockDim.x + threadIdx.x;
    if (i == 0) g_sum = 0.0;
    if (i < NB * SHW) g_invd[i] = __fdiv_rn(1.0f, __fadd_rn(depth[i], 1e-6f));
}

// Replicates XLA ElementalIrEmitter::EmitExpm1 followed by the "+ 1.0" in the loss:
//   em1 = |x| < 1e-5 ? x + (x*x)*0.5 : exp(x) - 1
//   return em1 + 1
// exp via double (correctly-rounded f32) — within one-quantum flip prob ~1e-5 of
// both __nv_expf (GPU XLA) and glibc expf (CPU XLA).
__device__ __forceinline__ float xla_expm1_p1(float x) {
    float em1;
    if (fabsf(x) < 1e-5f) {
        em1 = __fadd_rn(x, __fmul_rn(__fmul_rn(x, x), 0.5f));
    } else {
        float e = (float)exp((double)x);
        em1 = __fsub_rn(e, 1.0f);
    }
    return __fadd_rn(em1, 1.0f);
}

__global__ __launch_bounds__(256) void dgp_kernel(const float* __restrict__ sem) {
    const int c0 = blockIdx.x * 32 + threadIdx.x;
    const int r0 = blockIdx.y * 8  + threadIdx.y;
    const int b  = blockIdx.z;

    double acc = 0.0;
    if (r0 < HP && c0 < HP) {
        const int y = r0 + 2, x = c0 + 2;           // center pixel
        const float* __restrict__ sp  = sem + ((size_t)b * NC) * SHW + y * SW + x;
        const float* __restrict__ dpi = g_invd + b * SHW + y * SW + x;

        // cache center's 32 channels in registers
        float center[NC];
        #pragma unroll
        for (int ch = 0; ch < NC; ch++) center[ch] = sp[ch * SHW];

        #pragma unroll
        for (int di = -2; di <= 2; di++) {
            #pragma unroll
            for (int dj = -2; dj <= 2; dj++) {
                if (di == 0 && dj == 0) continue;   // center_mask
                const int off = di * SW + dj;
                // s = sum_c (a-b)^2, plain mul/add in channel order (no FMA contraction),
                // matching XLA's un-contracted reduce.
                float s = 0.0f;
                #pragma unroll
                for (int ch = 0; ch < NC; ch++) {
                    float d  = __fsub_rn(sp[ch * SHW + off], center[ch]);
                    s = __fadd_rn(s, __fmul_rn(d, d));
                }
                // f2 == 0 exactly for ssq > 25*ln2 = 17.33 (e^-ssq < 2^-25).
                // Gate with margin before doing anything expensive.
                if (s < 18.0f) {
                    float sd  = fmaxf(__fsqrt_rn(s), EPS_F);   // sem_diff clamp
                    float ssq = __fmul_rn(sd, sd);             // sem_diff ** 2
                    float dd  = fmaxf(fabsf(__fsub_rn(dpi[0], dpi[off])), EPS_F);
                    if (dd > EPS_F && sd > EPS_F) {            // reference mask m (pos always true)
                        float f1 = xla_expm1_p1(-__fdiv_rn(dd, 10.0f));
                        float f2 = xla_expm1_p1(-ssq);
                        acc += (double)__fmul_rn(f1, f2);
                    }
                }
            }
        }
    }

    // ~16 nonzero threads in the whole grid: skip reduction for all-zero warps.
    unsigned any = __ballot_sync(0xffffffffu, acc != 0.0);
    if (any) {
        #pragma unroll
        for (int o = 16; o > 0; o >>= 1)
            acc += __shfl_down_sync(0xffffffffu, acc, o);
        if ((threadIdx.x & 31) == 0 && acc != 0.0)
            atomicAdd(&g_sum, acc);
    }
}

__global__ void fin_kernel(float* __restrict__ out) {
    // divisor: mean over (B,B,k,k,P): sum_b1 duplicates (x2), /(25*B*B*P)
    //   -> S / (25*B*P) = S / 1,767,200
    out[0] = (float)(g_sum / 1767200.0);
}

extern "C" void kernel_launch(void* const* d_in, const int* in_sizes, int n_in,
                              void* d_out, int out_size) {
    const float* sem   = (const float*)d_in[0];  // (2, 32, 192, 192) f32
    const float* depth = (const float*)d_in[1];  // (2, 1, 192, 192) f32

    prep_kernel<<<(NB * SHW + 255) / 256, 256>>>(depth);

    dim3 blk(32, 8);
    dim3 grd((HP + 31) / 32, (HP + 7) / 8, NB);
    dgp_kernel<<<grd, blk>>>(sem);

    fin_kernel<<<1, 1>>>((float*)d_out);
}